// round 15
// baseline (speedup 1.0000x reference)
#include <cuda_runtime.h>

#define N_NODES 50000
#define N_EDGES 800000
#define N_GRAPHS 256
#define HID 128
#define BN_EPS 1e-5f

// ---------------- device scratch (no allocations allowed) ----------------
__device__ float g_agg[N_NODES * HID];
__device__ float g_x1[N_NODES * HID];
__device__ float g_h[N_NODES * HID];
__device__ float g_hcat[N_NODES * 2 * HID];
__device__ float g_stats[2 * HID];
__device__ float g_scale[HID];
__device__ float g_shift[HID];
__device__ float g_hg[N_GRAPHS * 2 * HID];
__device__ float g_m1[N_GRAPHS * HID];
__device__ float g_m2[N_GRAPHS * HID];
__device__ int g_deg[N_NODES];
__device__ int g_ptr[2][N_NODES + 1];
__device__ int g_cursor[N_NODES];
__device__ int g_csrc[2][N_EDGES];

// ---------------- f32x2 packed-FMA helpers (sm_100+) ----------------
static __device__ __forceinline__ unsigned long long pack2(float lo, float hi) {
    unsigned long long r;
    asm("mov.b64 %0, {%1, %2};" : "=l"(r) : "f"(lo), "f"(hi));
    return r;
}
static __device__ __forceinline__ void unpack2(unsigned long long v, float &lo, float &hi) {
    asm("mov.b64 {%0, %1}, %2;" : "=f"(lo), "=f"(hi) : "l"(v));
}
static __device__ __forceinline__ unsigned long long ffma2(
    unsigned long long a, unsigned long long b, unsigned long long c) {
    unsigned long long d;
    asm("fma.rn.f32x2 %0, %1, %2, %3;" : "=l"(d) : "l"(a), "l"(b), "l"(c));
    return d;
}

// ---------------- CSR construction (kernel-launch-only) ----------------

__global__ void zero_deg_kernel() {
    int i = blockIdx.x * 256 + threadIdx.x;
    if (i < N_NODES) g_deg[i] = 0;
}

__global__ void hist_kernel(const int *__restrict__ dst) {
    int e = blockIdx.x * 256 + threadIdx.x;  // exact grid: 3125 x 256
    atomicAdd(&g_deg[__ldg(dst + e)], 1);
}

// Single-block exclusive scan, 4 elements/thread (13 tiles of 4096).
__global__ void scan_kernel(int *__restrict__ ptr, int *__restrict__ cursor) {
    __shared__ int wsum[32];
    __shared__ int carry_s;
    int tid = threadIdx.x, lane = tid & 31, wid = tid >> 5;
    if (tid == 0) carry_s = 0;
    __syncthreads();
    const int TILES = (N_NODES + 4095) / 4096;  // 13
    for (int tile = 0; tile < TILES; tile++) {
        int carry = carry_s;
        int i = tile * 4096 + tid * 4;
        int v0 = (i + 0 < N_NODES) ? g_deg[i + 0] : 0;
        int v1 = (i + 1 < N_NODES) ? g_deg[i + 1] : 0;
        int v2 = (i + 2 < N_NODES) ? g_deg[i + 2] : 0;
        int v3 = (i + 3 < N_NODES) ? g_deg[i + 3] : 0;
        int s = v0 + v1 + v2 + v3;
        int x = s;
#pragma unroll
        for (int off = 1; off < 32; off <<= 1) {
            int t = __shfl_up_sync(0xffffffffu, x, off);
            if (lane >= off) x += t;
        }
        if (lane == 31) wsum[wid] = x;
        __syncthreads();
        if (wid == 0) {
            int w = wsum[lane];
#pragma unroll
            for (int off = 1; off < 32; off <<= 1) {
                int t = __shfl_up_sync(0xffffffffu, w, off);
                if (lane >= off) w += t;
            }
            wsum[lane] = w;
        }
        __syncthreads();
        int wbase = (wid > 0) ? wsum[wid - 1] : 0;
        int e0 = (x - s) + wbase + carry;  // exclusive prefix for v0
        int e1 = e0 + v0, e2 = e1 + v1, e3 = e2 + v2;
        if (i + 0 < N_NODES) { ptr[i + 0] = e0; cursor[i + 0] = e0; }
        if (i + 1 < N_NODES) { ptr[i + 1] = e1; cursor[i + 1] = e1; }
        if (i + 2 < N_NODES) { ptr[i + 2] = e2; cursor[i + 2] = e2; }
        if (i + 3 < N_NODES) { ptr[i + 3] = e3; cursor[i + 3] = e3; }
        __syncthreads();
        if (tid == 0) carry_s = carry + wsum[31];
        __syncthreads();
    }
    if (tid == 0) ptr[N_NODES] = carry_s;  // total = N_EDGES
}

__global__ void reorder_kernel(const int *__restrict__ src,
                               const int *__restrict__ dst,
                               int *__restrict__ csrc) {
    int e = blockIdx.x * 256 + threadIdx.x;  // exact grid
    int d = __ldg(dst + e);
    int pos = atomicAdd(&g_cursor[d], 1);
    csrc[pos] = __ldg(src + e);
}

// ---------------- aggregation (one warp per node, CSR gather) ----------------
__global__ void __launch_bounds__(256) gather_agg_kernel(
    const float *__restrict__ hin, const int *__restrict__ ptr,
    const int *__restrict__ csrc, const float *__restrict__ eps, int eidx) {
    if (blockIdx.x == 0 && threadIdx.x < 2 * HID) g_stats[threadIdx.x] = 0.0f;
    int node = (blockIdx.x * 256 + threadIdx.x) >> 5;  // exact: 6250*8 = 50000
    int lane = threadIdx.x & 31;
    float e1 = 1.0f + __ldg(eps + eidx);
    float4 acc = __ldg((const float4 *)(hin + (size_t)node * HID) + lane);
    acc.x *= e1; acc.y *= e1; acc.z *= e1; acc.w *= e1;
    int beg = __ldg(ptr + node), end = __ldg(ptr + node + 1);
    for (int base = beg; base < end; base += 32) {
        int sidx = (base + lane < end) ? __ldg(csrc + base + lane) : 0;
        int m = min(32, end - base);
#pragma unroll 4
        for (int j = 0; j < m; j++) {
            int s = __shfl_sync(0xffffffffu, sidx, j);
            float4 v = __ldg((const float4 *)(hin + (size_t)s * HID) + lane);
            acc.x += v.x; acc.y += v.y; acc.z += v.z; acc.w += v.w;
        }
    }
    ((float4 *)(g_agg + (size_t)node * HID))[lane] = acc;
}

// ---------------- GEMM: 128x128 tile, 256 threads, 8x8 per thread ----------------
// A smem stored k-major (transposed) with pitch 132; W smem k-major pitch 128.
// Per-thread columns: {tx*4..+3} and {64+tx*4..+3} -> conflict-free W reads.
#define APITCH 132
__global__ void __launch_bounds__(256) gemm_kernel(
    const float *__restrict__ A, const float *__restrict__ W,
    const float *__restrict__ bias, float *__restrict__ out,
    int ostride, int ocol, int apply_bn, int relu_out, int do_stats) {
    __shared__ float Ash[32 * APITCH];  // [k][row] 16.5 KB
    __shared__ float Wsh[32 * 128];     // [k][col] 16 KB
    int tid = threadIdx.x;
    int tx = tid & 15;   // 16 col groups
    int ty = tid >> 4;   // 16 row groups (8 rows each)
    int rowBase = blockIdx.x * 128;
    int ca = tx * 4;        // first 4 columns
    int cb = 64 + tx * 4;   // second 4 columns

    unsigned long long acc[8][4];
    unsigned long long zz = pack2(0.0f, 0.0f);
#pragma unroll
    for (int r = 0; r < 8; r++)
#pragma unroll
        for (int c = 0; c < 4; c++) acc[r][c] = zz;

    for (int kk = 0; kk < HID; kk += 32) {
        // ---- A tile: 128 rows x 32 k, transposed store, fused BN+ReLU ----
#pragma unroll
        for (int i = tid; i < 1024; i += 256) {
            int row = i >> 3, c4 = i & 7;
            int grow = rowBase + row;
            float4 v = make_float4(0.0f, 0.0f, 0.0f, 0.0f);
            if (grow < N_NODES)
                v = __ldg((const float4 *)(A + (size_t)grow * HID + kk) + c4);
            if (apply_bn) {
                int c = kk + c4 * 4;
                v.x = fmaxf(v.x * g_scale[c + 0] + g_shift[c + 0], 0.0f);
                v.y = fmaxf(v.y * g_scale[c + 1] + g_shift[c + 1], 0.0f);
                v.z = fmaxf(v.z * g_scale[c + 2] + g_shift[c + 2], 0.0f);
                v.w = fmaxf(v.w * g_scale[c + 3] + g_shift[c + 3], 0.0f);
            }
            Ash[(c4 * 4 + 0) * APITCH + row] = v.x;
            Ash[(c4 * 4 + 1) * APITCH + row] = v.y;
            Ash[(c4 * 4 + 2) * APITCH + row] = v.z;
            Ash[(c4 * 4 + 3) * APITCH + row] = v.w;
        }
        // ---- W tile: 32 k x 128 cols, direct copy ----
#pragma unroll
        for (int i = tid; i < 1024; i += 256) {
            int wr = i >> 5, wc4 = i & 31;
            *(float4 *)&Wsh[wr * 128 + wc4 * 4] =
                __ldg((const float4 *)(W + (size_t)(kk + wr) * HID) + wc4);
        }
        __syncthreads();
        // ---- compute: per k, 4 LDS.128 + 32 FFMA2 per thread ----
#pragma unroll 8
        for (int k = 0; k < 32; k++) {
            float4 a0 = *(const float4 *)&Ash[k * APITCH + ty * 8];
            float4 a1 = *(const float4 *)&Ash[k * APITCH + ty * 8 + 4];
            float4 w0 = *(const float4 *)&Wsh[k * 128 + ca];
            float4 w1 = *(const float4 *)&Wsh[k * 128 + cb];
            unsigned long long wp[4] = {pack2(w0.x, w0.y), pack2(w0.z, w0.w),
                                        pack2(w1.x, w1.y), pack2(w1.z, w1.w)};
            float ar[8] = {a0.x, a0.y, a0.z, a0.w, a1.x, a1.y, a1.z, a1.w};
#pragma unroll
            for (int r = 0; r < 8; r++) {
                unsigned long long aa = pack2(ar[r], ar[r]);
#pragma unroll
                for (int c = 0; c < 4; c++) acc[r][c] = ffma2(aa, wp[c], acc[r][c]);
            }
        }
        __syncthreads();
    }

    // ---- epilogue ----
    float ba0 = __ldg(bias + ca + 0), ba1 = __ldg(bias + ca + 1);
    float ba2 = __ldg(bias + ca + 2), ba3 = __ldg(bias + ca + 3);
    float bb0 = __ldg(bias + cb + 0), bb1 = __ldg(bias + cb + 1);
    float bb2 = __ldg(bias + cb + 2), bb3 = __ldg(bias + cb + 3);
    float sA[4] = {0, 0, 0, 0}, qA[4] = {0, 0, 0, 0};
    float sB[4] = {0, 0, 0, 0}, qB[4] = {0, 0, 0, 0};
#pragma unroll
    for (int r = 0; r < 8; r++) {
        int grow = rowBase + ty * 8 + r;
        if (grow < N_NODES) {
            float y0, y1, y2, y3, z0, z1, z2, z3;
            unpack2(acc[r][0], y0, y1); unpack2(acc[r][1], y2, y3);
            unpack2(acc[r][2], z0, z1); unpack2(acc[r][3], z2, z3);
            y0 += ba0; y1 += ba1; y2 += ba2; y3 += ba3;
            z0 += bb0; z1 += bb1; z2 += bb2; z3 += bb3;
            if (relu_out) {
                y0 = fmaxf(y0, 0.0f); y1 = fmaxf(y1, 0.0f);
                y2 = fmaxf(y2, 0.0f); y3 = fmaxf(y3, 0.0f);
                z0 = fmaxf(z0, 0.0f); z1 = fmaxf(z1, 0.0f);
                z2 = fmaxf(z2, 0.0f); z3 = fmaxf(z3, 0.0f);
            }
            float *op = out + (size_t)grow * ostride + ocol;
            *(float4 *)(op + ca) = make_float4(y0, y1, y2, y3);
            *(float4 *)(op + cb) = make_float4(z0, z1, z2, z3);
            if (do_stats) {
                sA[0] += y0; sA[1] += y1; sA[2] += y2; sA[3] += y3;
                qA[0] += y0 * y0; qA[1] += y1 * y1; qA[2] += y2 * y2; qA[3] += y3 * y3;
                sB[0] += z0; sB[1] += z1; sB[2] += z2; sB[3] += z3;
                qB[0] += z0 * z0; qB[1] += z1 * z1; qB[2] += z2 * z2; qB[3] += z3 * z3;
            }
        }
    }
    if (do_stats) {
        float *sred = Ash;  // reuse: [0..127]=sum, [128..255]=sumsq
        sred[tid] = 0.0f;
        __syncthreads();
#pragma unroll
        for (int j = 0; j < 4; j++) {
            atomicAdd(&sred[ca + j], sA[j]);
            atomicAdd(&sred[cb + j], sB[j]);
            atomicAdd(&sred[128 + ca + j], qA[j]);
            atomicAdd(&sred[128 + cb + j], qB[j]);
        }
        __syncthreads();
        atomicAdd(&g_stats[tid], sred[tid]);
    }
}

__global__ void bn_finalize_kernel(const float *__restrict__ gamma,
                                   const float *__restrict__ beta) {
    int c = threadIdx.x;  // 128 threads
    float inv = 1.0f / (float)N_NODES;
    float mu = g_stats[c] * inv;
    float var = g_stats[HID + c] * inv - mu * mu;
    float rs = rsqrtf(var + BN_EPS);
    float sc = rs * __ldg(gamma + c);
    g_scale[c] = sc;
    g_shift[c] = __ldg(beta + c) - mu * sc;
}

// ---------------- readout: graph_ids is SORTED -> contiguous segments ----------------
static __device__ __forceinline__ int lower_bound_dev(const int *a, int n, int key) {
    int lo = 0, hi = n;
    while (lo < hi) {
        int mid = (lo + hi) >> 1;
        if (__ldg(a + mid) < key) lo = mid + 1; else hi = mid;
    }
    return lo;
}

__global__ void readout_kernel(const int *__restrict__ gid) {
    __shared__ int s_rng[2];
    int g = blockIdx.x, t = threadIdx.x;  // 256 blocks x 256 threads
    if (t < 2) s_rng[t] = lower_bound_dev(gid, N_NODES, g + t);
    __syncthreads();
    int beg = s_rng[0], end = s_rng[1];
    float acc = 0.0f;
    for (int n = beg; n < end; n++)
        acc += __ldg(g_hcat + (size_t)n * (2 * HID) + t);
    g_hg[(size_t)g * (2 * HID) + t] = acc;
}

// ---------------- tiny MLP head ----------------
__global__ void mlp_kernel(const float *__restrict__ X, int K,
                           const float *__restrict__ W,
                           const float *__restrict__ b,
                           float *__restrict__ Y, int relu) {
    __shared__ float row[256];
    int g = blockIdx.x, t = threadIdx.x;  // 128 threads
    for (int k = t; k < K; k += 128) row[k] = __ldg(X + (size_t)g * K + k);
    __syncthreads();
    float acc = 0.0f;
#pragma unroll 8
    for (int k = 0; k < K; k++) acc = fmaf(row[k], __ldg(W + (size_t)k * HID + t), acc);
    acc += __ldg(b + t);
    if (relu) acc = fmaxf(acc, 0.0f);
    Y[(size_t)g * HID + t] = acc;
}

__global__ void mlp_out_kernel(const float *__restrict__ W3,
                               const float *__restrict__ b3,
                               float *__restrict__ out) {
    __shared__ float w[HID];
    int t = threadIdx.x;  // 256 threads
    if (t < HID) w[t] = __ldg(W3 + t);
    __syncthreads();
    float acc = 0.0f;
#pragma unroll 8
    for (int k = 0; k < HID; k++) acc = fmaf(g_m2[(size_t)t * HID + k], w[k], acc);
    out[t] = acc + __ldg(b3);
}

// ---------------- launch ----------------
extern "C" void kernel_launch(void *const *d_in, const int *in_sizes, int n_in,
                              void *d_out, int out_size) {
    const float *feats = (const float *)d_in[0];
    const int *src = (const int *)d_in[1];
    const int *dst = (const int *)d_in[2];
    const int *gid = (const int *)d_in[3];
    int base = (in_sizes[4] == 4) ? 4 : 5;  // d_in[4] = scalar n_graphs or eps
    const float *eps = (const float *)d_in[base + 0];
    const float *Wa  = (const float *)d_in[base + 1];
    const float *ba  = (const float *)d_in[base + 2];
    const float *bng = (const float *)d_in[base + 3];
    const float *bnb = (const float *)d_in[base + 4];
    const float *Wb  = (const float *)d_in[base + 5];
    const float *bb  = (const float *)d_in[base + 6];
    const float *oW1 = (const float *)d_in[base + 7];
    const float *ob1 = (const float *)d_in[base + 8];
    const float *oW2 = (const float *)d_in[base + 9];
    const float *ob2 = (const float *)d_in[base + 10];
    const float *oW3 = (const float *)d_in[base + 11];
    const float *ob3 = (const float *)d_in[base + 12];
    float *out = (float *)d_out;

    void *p;
    cudaGetSymbolAddress(&p, g_agg);   float *agg  = (float *)p;
    cudaGetSymbolAddress(&p, g_x1);    float *x1   = (float *)p;
    cudaGetSymbolAddress(&p, g_h);     float *h    = (float *)p;
    cudaGetSymbolAddress(&p, g_hcat);  float *hcat = (float *)p;
    cudaGetSymbolAddress(&p, g_hg);    float *hg   = (float *)p;
    cudaGetSymbolAddress(&p, g_m1);    float *m1   = (float *)p;
    cudaGetSymbolAddress(&p, g_m2);    float *m2   = (float *)p;
    cudaGetSymbolAddress(&p, g_ptr);   int *ptr0   = (int *)p;
    cudaGetSymbolAddress(&p, g_cursor);int *cursor = (int *)p;
    cudaGetSymbolAddress(&p, g_csrc);  int *csrc0  = (int *)p;

    const int GEMM_BLOCKS = (N_NODES + 127) / 128;     // 391
    const int EDGE_BLOCKS = N_EDGES / 256;             // 3125 (exact)
    const int GATHER_BLOCKS = N_NODES / 8;             // 6250 (exact)
    const int DEG_BLOCKS = (N_NODES + 255) / 256;      // 196

    // ---- build dst-CSR per edge type (used by both layers) ----
    for (int e = 0; e < 2; e++) {
        int *ptr_e = ptr0 + e * (N_NODES + 1);
        int *csrc_e = csrc0 + e * N_EDGES;
        zero_deg_kernel<<<DEG_BLOCKS, 256>>>();
        hist_kernel<<<EDGE_BLOCKS, 256>>>(dst + e * N_EDGES);
        scan_kernel<<<1, 1024>>>(ptr_e, cursor);
        reorder_kernel<<<EDGE_BLOCKS, 256>>>(src + e * N_EDGES, dst + e * N_EDGES,
                                             csrc_e);
    }

    for (int e = 0; e < 2; e++) {
        int *ptr_e = ptr0 + e * (N_NODES + 1);
        int *csrc_e = csrc0 + e * N_EDGES;
        const float *hin = feats;
        for (int l = 0; l < 2; l++) {
            int idx = e * 2 + l;
            gather_agg_kernel<<<GATHER_BLOCKS, 256>>>(hin, ptr_e, csrc_e, eps, idx);
            gemm_kernel<<<GEMM_BLOCKS, 256>>>(agg, Wa + (size_t)idx * HID * HID,
                                              ba + idx * HID, x1, HID, 0,
                                              /*bn*/0, /*relu*/0, /*stats*/1);
            bn_finalize_kernel<<<1, HID>>>(bng + idx * HID, bnb + idx * HID);
            if (l == 0) {
                gemm_kernel<<<GEMM_BLOCKS, 256>>>(x1, Wb + (size_t)idx * HID * HID,
                                                  bb + idx * HID, h, HID, 0,
                                                  /*bn*/1, /*relu*/1, /*stats*/0);
            } else {
                gemm_kernel<<<GEMM_BLOCKS, 256>>>(x1, Wb + (size_t)idx * HID * HID,
                                                  bb + idx * HID, hcat, 2 * HID,
                                                  e * HID,
                                                  /*bn*/1, /*relu*/0, /*stats*/0);
            }
            hin = h;
        }
    }

    readout_kernel<<<N_GRAPHS, 2 * HID>>>(gid);
    mlp_kernel<<<N_GRAPHS, HID>>>(hg, 2 * HID, oW1, ob1, m1, 1);
    mlp_kernel<<<N_GRAPHS, HID>>>(m1, HID, oW2, ob2, m2, 1);
    mlp_out_kernel<<<1, N_GRAPHS>>>(oW3, ob3, out);
}